// round 9
// baseline (speedup 1.0000x reference)
#include <cuda_runtime.h>
#include <cuda_bf16.h>
#include <cstdint>

#define N_NODES 100000
#define N_EDGES 600000
#define DIM 128
#define KTOT 640   // 512 (4 bases x 128) + 128 (root)
#define SCAN_BLOCKS 98
#define AGG_BLOCKS 12500
#define QSCALE 16128.0f   // 126*128: hi in [-126,126], lo in [-64,64)

// ---------------- scratch (static device globals; no runtime alloc) ----------------
__device__ float g_h1[(size_t)N_NODES * DIM];
__device__ int8_t g_A1h[(size_t)N_NODES * KTOT];
__device__ int8_t g_A1l[(size_t)N_NODES * KTOT];
__device__ int8_t g_A2h[(size_t)N_NODES * KTOT];
__device__ int8_t g_A2l[(size_t)N_NODES * KTOT];
__device__ float g_sA1[N_NODES];
__device__ float g_sA2[N_NODES];
__device__ int8_t g_W1h[128 * KTOT];   // [n][k]
__device__ int8_t g_W1l[128 * KTOT];
__device__ int8_t g_W2h[128 * KTOT];
__device__ int8_t g_W2l[128 * KTOT];
__device__ float g_sW1[128];
__device__ float g_sW2[128];
__device__ float4 g_coeff1[N_EDGES];
__device__ float4 g_coeff2[N_EDGES];
__device__ int   g_csr_src[N_EDGES];
__device__ int   g_csr_esrc[N_EDGES];
__device__ int   g_deg[N_NODES];
__device__ int   g_rowptr[N_NODES + 1];
__device__ int   g_cursor[N_NODES];
__device__ float g_invdeg[N_NODES];
__device__ unsigned long long g_scan_state[SCAN_BLOCKS];
__device__ int   g_ticket;

// ---------------- helpers ----------------
__device__ __forceinline__ uint32_t smem_u32(const void* p) {
    uint32_t a;
    asm("{ .reg .u64 t; cvta.to.shared.u64 t, %1; cvt.u32.u64 %0, t; }" : "=r"(a) : "l"(p));
    return a;
}
__device__ __forceinline__ void ldm_x4(uint32_t* r, uint32_t addr) {
    asm volatile("ldmatrix.sync.aligned.m8n8.x4.shared.b16 {%0,%1,%2,%3}, [%4];"
                 : "=r"(r[0]), "=r"(r[1]), "=r"(r[2]), "=r"(r[3]) : "r"(addr));
}
__device__ __forceinline__ void imma16832(int* c, const uint32_t* a, const uint32_t* b) {
    asm volatile("mma.sync.aligned.m16n8k32.row.col.s32.s8.s8.s32 "
                 "{%0,%1,%2,%3}, {%4,%5,%6,%7}, {%8,%9}, {%0,%1,%2,%3};"
                 : "+r"(c[0]), "+r"(c[1]), "+r"(c[2]), "+r"(c[3])
                 : "r"(a[0]), "r"(a[1]), "r"(a[2]), "r"(a[3]), "r"(b[0]), "r"(b[1]));
}
__device__ __forceinline__ void cp16(uint32_t dst, const void* src) {
    asm volatile("cp.async.cg.shared.global [%0], [%1], 16;" :: "r"(dst), "l"(src));
}
#define CP_COMMIT() asm volatile("cp.async.commit_group;" ::: "memory")
#define CP_WAIT(N)  asm volatile("cp.async.wait_group %0;" :: "n"(N) : "memory")

__device__ __forceinline__ uint32_t pack4(int a, int b, int c, int d) {
    return (uint32_t)(a & 0xff) | ((uint32_t)(b & 0xff) << 8) |
           ((uint32_t)(c & 0xff) << 16) | ((uint32_t)(d & 0xff) << 24);
}
__device__ __forceinline__ void quant_seg(float4 v, float f, uint32_t& uh, uint32_t& ul) {
    int q0 = __float2int_rn(v.x * f), q1 = __float2int_rn(v.y * f);
    int q2 = __float2int_rn(v.z * f), q3 = __float2int_rn(v.w * f);
    int h0 = (q0 + 64) >> 7, h1 = (q1 + 64) >> 7;
    int h2 = (q2 + 64) >> 7, h3 = (q3 + 64) >> 7;
    uh = pack4(h0, h1, h2, h3);
    ul = pack4(q0 - (h0 << 7), q1 - (h1 << 7), q2 - (h2 << 7), q3 - (h3 << 7));
}

// ---------------- 1: zero ----------------
__global__ void k_zero() {
    int i = blockIdx.x * blockDim.x + threadIdx.x;
    if (i < N_NODES) g_deg[i] = 0;
    if (i < SCAN_BLOCKS) g_scan_state[i] = 0ull;
    if (i == 0) { g_ticket = 0; g_rowptr[N_NODES] = N_EDGES; }
}

// ---------------- 2: histogram ----------------
__global__ void k_hist(const int* __restrict__ dst) {
    int i = blockIdx.x * blockDim.x + threadIdx.x;
    if (i < N_EDGES) atomicAdd(&g_deg[dst[i]], 1);
}

// ---------------- 3: weight quantization (per-column scale, both layers) ----------------
__global__ void k_quantw(const float* __restrict__ basis1, const float* __restrict__ root1,
                         const float* __restrict__ basis2, const float* __restrict__ root2) {
    __shared__ float sm[128];
    int b = blockIdx.x;           // 0..255
    int which = b >> 7;
    int n = b & 127;
    int t = threadIdx.x;          // 128 threads
    const float* basis = which ? basis2 : basis1;
    const float* root  = which ? root2  : root1;
    float vals[5];
    float m = 0.f;
    #pragma unroll
    for (int i = 0; i < 5; i++) {
        int k = t + i * 128;
        float w = (k < 512) ? basis[(size_t)k * 128 + n] : root[(size_t)(k - 512) * 128 + n];
        vals[i] = w;
        m = fmaxf(m, fabsf(w));
    }
    sm[t] = m;
    __syncthreads();
    #pragma unroll
    for (int s = 64; s > 0; s >>= 1) {
        if (t < s) sm[t] = fmaxf(sm[t], sm[t + s]);
        __syncthreads();
    }
    float mx = fmaxf(sm[0], 1e-30f);
    float f = QSCALE / mx;
    int8_t* Wh = which ? g_W2h : g_W1h;
    int8_t* Wl = which ? g_W2l : g_W1l;
    if (t == 0) (which ? g_sW2 : g_sW1)[n] = mx / QSCALE;
    #pragma unroll
    for (int i = 0; i < 5; i++) {
        int k = t + i * 128;
        int q = __float2int_rn(vals[i] * f);
        int h = (q + 64) >> 7;
        Wh[n * KTOT + k] = (int8_t)h;
        Wl[n * KTOT + k] = (int8_t)(q - (h << 7));
    }
}

// ---------------- 4: single-pass decoupled-lookback scan ----------------
__global__ void k_scan() {
    __shared__ int sh[1024];
    __shared__ int sbid;
    __shared__ int sexcl;
    int t = threadIdx.x;
    if (t == 0) sbid = atomicAdd(&g_ticket, 1);
    __syncthreads();
    int b = sbid;
    int i = b * 1024 + t;
    int v = (i < N_NODES) ? g_deg[i] : 0;
    sh[t] = v;
    __syncthreads();
    #pragma unroll
    for (int off = 1; off < 1024; off <<= 1) {
        int x = (t >= off) ? sh[t - off] : 0;
        __syncthreads();
        sh[t] += x;
        __syncthreads();
    }
    if (t == 0) {
        int total = sh[1023];
        int excl = 0;
        if (b == 0) {
            atomicExch(&g_scan_state[0], ((unsigned long long)total << 2) | 2ull);
        } else {
            atomicExch(&g_scan_state[b], ((unsigned long long)total << 2) | 1ull);
            int j = b - 1;
            long long run = 0;
            while (true) {
                unsigned long long s = atomicAdd(&g_scan_state[j], 0ull);
                unsigned f = (unsigned)(s & 3ull);
                if (f == 0) continue;
                run += (long long)(s >> 2);
                if (f == 2) break;
                j--;
            }
            excl = (int)run;
            atomicExch(&g_scan_state[b], ((unsigned long long)(excl + total) << 2) | 2ull);
        }
        sexcl = excl;
    }
    __syncthreads();
    if (i < N_NODES) {
        int rp = sexcl + sh[t] - v;
        g_rowptr[i] = rp;
        g_cursor[i] = rp;
        g_invdeg[i] = 1.0f / fmaxf((float)v, 1.0f);
    }
}

// ---------------- 5: scatter + CSR coefficients + entity-resolved src ----------------
__global__ void k_scatter(const int* __restrict__ dst, const int* __restrict__ src,
                          const int* __restrict__ entity,
                          const int* __restrict__ etype, const float* __restrict__ enorm,
                          const float4* __restrict__ att1, const float4* __restrict__ att2) {
    int e = blockIdx.x * blockDim.x + threadIdx.x;
    if (e >= N_EDGES) return;
    int s = src[e];
    int pos = atomicAdd(&g_cursor[dst[e]], 1);
    g_csr_src[pos] = s;
    g_csr_esrc[pos] = entity[s];
    int t = etype[e];
    float n = enorm[e];
    float4 a1 = att1[t];
    float4 a2 = att2[t];
    g_coeff1[pos] = make_float4(a1.x * n, a1.y * n, a1.z * n, a1.w * n);
    g_coeff2[pos] = make_float4(a2.x * n, a2.y * n, a2.z * n, a2.w * n);
}

// ---------------- aggregation core (R4-proven) ----------------
__device__ __forceinline__ void agg_node(int node, int lane,
                                         const float4* __restrict__ X4,
                                         const int* __restrict__ sidx,
                                         const float4* __restrict__ cf,
                                         float4& s0, float4& s1, float4& s2, float4& s3) {
    int beg = g_rowptr[node], end = g_rowptr[node + 1];
    int p = beg;
    for (; p + 2 <= end; p += 2) {
        float4 ca = cf[p];
        float4 cb = cf[p + 1];
        int sa = sidx[p];
        int sb = sidx[p + 1];
        float4 xa = X4[(size_t)sa * 32 + lane];
        float4 xb = X4[(size_t)sb * 32 + lane];
        s0.x = fmaf(ca.x, xa.x, s0.x); s0.y = fmaf(ca.x, xa.y, s0.y);
        s0.z = fmaf(ca.x, xa.z, s0.z); s0.w = fmaf(ca.x, xa.w, s0.w);
        s1.x = fmaf(ca.y, xa.x, s1.x); s1.y = fmaf(ca.y, xa.y, s1.y);
        s1.z = fmaf(ca.y, xa.z, s1.z); s1.w = fmaf(ca.y, xa.w, s1.w);
        s2.x = fmaf(ca.z, xa.x, s2.x); s2.y = fmaf(ca.z, xa.y, s2.y);
        s2.z = fmaf(ca.z, xa.z, s2.z); s2.w = fmaf(ca.z, xa.w, s2.w);
        s3.x = fmaf(ca.w, xa.x, s3.x); s3.y = fmaf(ca.w, xa.y, s3.y);
        s3.z = fmaf(ca.w, xa.z, s3.z); s3.w = fmaf(ca.w, xa.w, s3.w);
        s0.x = fmaf(cb.x, xb.x, s0.x); s0.y = fmaf(cb.x, xb.y, s0.y);
        s0.z = fmaf(cb.x, xb.z, s0.z); s0.w = fmaf(cb.x, xb.w, s0.w);
        s1.x = fmaf(cb.y, xb.x, s1.x); s1.y = fmaf(cb.y, xb.y, s1.y);
        s1.z = fmaf(cb.y, xb.z, s1.z); s1.w = fmaf(cb.y, xb.w, s1.w);
        s2.x = fmaf(cb.z, xb.x, s2.x); s2.y = fmaf(cb.z, xb.y, s2.y);
        s2.z = fmaf(cb.z, xb.z, s2.z); s2.w = fmaf(cb.z, xb.w, s2.w);
        s3.x = fmaf(cb.w, xb.x, s3.x); s3.y = fmaf(cb.w, xb.y, s3.y);
        s3.z = fmaf(cb.w, xb.z, s3.z); s3.w = fmaf(cb.w, xb.w, s3.w);
    }
    if (p < end) {
        float4 c = cf[p];
        int sn = sidx[p];
        float4 xv = X4[(size_t)sn * 32 + lane];
        s0.x = fmaf(c.x, xv.x, s0.x); s0.y = fmaf(c.x, xv.y, s0.y);
        s0.z = fmaf(c.x, xv.z, s0.z); s0.w = fmaf(c.x, xv.w, s0.w);
        s1.x = fmaf(c.y, xv.x, s1.x); s1.y = fmaf(c.y, xv.y, s1.y);
        s1.z = fmaf(c.y, xv.z, s1.z); s1.w = fmaf(c.y, xv.w, s1.w);
        s2.x = fmaf(c.z, xv.x, s2.x); s2.y = fmaf(c.z, xv.y, s2.y);
        s2.z = fmaf(c.z, xv.z, s2.z); s2.w = fmaf(c.z, xv.w, s2.w);
        s3.x = fmaf(c.w, xv.x, s3.x); s3.y = fmaf(c.w, xv.y, s3.y);
        s3.z = fmaf(c.w, xv.z, s3.z); s3.w = fmaf(c.w, xv.w, s3.w);
    }
}

// quantized row store: 5 segments (4 basis + root), per-row scale by warp max
__device__ __forceinline__ void agg_store_q(int node, int lane, float d,
                                            float4 s0, float4 s1, float4 s2, float4 s3,
                                            float4 xs,
                                            int8_t* __restrict__ Ah, int8_t* __restrict__ Al,
                                            float* __restrict__ sA) {
    s0.x *= d; s0.y *= d; s0.z *= d; s0.w *= d;
    s1.x *= d; s1.y *= d; s1.z *= d; s1.w *= d;
    s2.x *= d; s2.y *= d; s2.z *= d; s2.w *= d;
    s3.x *= d; s3.y *= d; s3.z *= d; s3.w *= d;
    float m = fmaxf(fmaxf(fmaxf(fabsf(s0.x), fabsf(s0.y)), fmaxf(fabsf(s0.z), fabsf(s0.w))),
                    fmaxf(fmaxf(fabsf(s1.x), fabsf(s1.y)), fmaxf(fabsf(s1.z), fabsf(s1.w))));
    m = fmaxf(m, fmaxf(fmaxf(fabsf(s2.x), fabsf(s2.y)), fmaxf(fabsf(s2.z), fabsf(s2.w))));
    m = fmaxf(m, fmaxf(fmaxf(fabsf(s3.x), fabsf(s3.y)), fmaxf(fabsf(s3.z), fabsf(s3.w))));
    m = fmaxf(m, fmaxf(fmaxf(fabsf(xs.x), fabsf(xs.y)), fmaxf(fabsf(xs.z), fabsf(xs.w))));
    #pragma unroll
    for (int off = 16; off > 0; off >>= 1)
        m = fmaxf(m, __shfl_xor_sync(0xffffffffu, m, off));
    m = fmaxf(m, 1e-30f);
    float f = QSCALE / m;
    if (lane == 0) sA[node] = m / QSCALE;
    size_t base = (size_t)node * KTOT + 4 * lane;
    uint32_t uh, ul;
    quant_seg(s0, f, uh, ul);
    *(uint32_t*)(Ah + base)       = uh; *(uint32_t*)(Al + base)       = ul;
    quant_seg(s1, f, uh, ul);
    *(uint32_t*)(Ah + base + 128) = uh; *(uint32_t*)(Al + base + 128) = ul;
    quant_seg(s2, f, uh, ul);
    *(uint32_t*)(Ah + base + 256) = uh; *(uint32_t*)(Al + base + 256) = ul;
    quant_seg(s3, f, uh, ul);
    *(uint32_t*)(Ah + base + 384) = uh; *(uint32_t*)(Al + base + 384) = ul;
    quant_seg(xs, f, uh, ul);
    *(uint32_t*)(Ah + base + 512) = uh; *(uint32_t*)(Al + base + 512) = ul;
}

// ---------------- 6: layer-1 aggregation (entity_table gathers; writes full A1 row) ----------------
__global__ void k_agg0(const float4* __restrict__ tbl, const int* __restrict__ entity) {
    int gw = (blockIdx.x * blockDim.x + threadIdx.x) >> 5;
    int lane = threadIdx.x & 31;
    if (gw >= N_NODES) return;
    float4 s0 = make_float4(0.f, 0.f, 0.f, 0.f);
    float4 s1 = s0, s2 = s0, s3 = s0;
    agg_node(gw, lane, tbl, g_csr_esrc, g_coeff1, s0, s1, s2, s3);
    float4 xs = tbl[(size_t)entity[gw] * 32 + lane];
    agg_store_q(gw, lane, g_invdeg[gw], s0, s1, s2, s3, xs, g_A1h, g_A1l, g_sA1);
}

// ---------------- 8: layer-2 aggregation (+ relation_emb copy tail) ----------------
__global__ void k_agg1(const float* __restrict__ rel, float* __restrict__ out) {
    if (blockIdx.x >= AGG_BLOCKS) {
        int i = (blockIdx.x - AGG_BLOCKS) * 256 + threadIdx.x;
        for (; i < 500 * 128; i += 32 * 256)
            out[(size_t)N_NODES * 128 + i] = rel[i];
        return;
    }
    int gw = (blockIdx.x * blockDim.x + threadIdx.x) >> 5;
    int lane = threadIdx.x & 31;
    if (gw >= N_NODES) return;
    float4 s0 = make_float4(0.f, 0.f, 0.f, 0.f);
    float4 s1 = s0, s2 = s0, s3 = s0;
    agg_node(gw, lane, (const float4*)g_h1, g_csr_src, g_coeff2, s0, s1, s2, s3);
    float4 xs = ((const float4*)g_h1)[(size_t)gw * 32 + lane];
    agg_store_q(gw, lane, g_invdeg[gw], s0, s1, s2, s3, xs, g_A2h, g_A2l, g_sA2);
}

// ---------------- 7/9: IMMA GEMM, cp.async double-buffered, 512 threads ----------------
// CTA tile 128x128, BK=64 int8. 16 warps (4M x 4N), warp tile 32x32.
// Tiles: 128 rows x 80B stride (64B data) = 10240B each; 4 tiles x 2 buffers.
#define TILE_B 10240
#define BUF_B  (4 * TILE_B)
#define SMEM_GEMM (2 * BUF_B)   // 81920

__global__ __launch_bounds__(512, 1) void k_gemm_imma(
    int layer, const float* __restrict__ bias, float* __restrict__ out_param, int do_relu)
{
    extern __shared__ char smem[];
    uint32_t sbase = smem_u32(smem);
    const int8_t* Ah = (layer == 0) ? g_A1h : g_A2h;
    const int8_t* Al = (layer == 0) ? g_A1l : g_A2l;
    const int8_t* Wh = (layer == 0) ? g_W1h : g_W2h;
    const int8_t* Wl = (layer == 0) ? g_W1l : g_W2l;
    const float*  sA = (layer == 0) ? g_sA1 : g_sA2;
    const float*  sW = (layer == 0) ? g_sW1 : g_sW2;
    float* out = (layer == 0) ? g_h1 : out_param;

    int tid = threadIdx.x;
    int wid = tid >> 5;
    int lane = tid & 31;
    int bm = blockIdx.x * 128;
    int wm0 = (wid >> 2) * 32;   // 0,32,64,96
    int wn0 = (wid & 3) * 32;    // 0,32,64,96

    int acc1[2][4][4], acc2[2][4][4];
    #pragma unroll
    for (int i = 0; i < 2; i++)
        #pragma unroll
        for (int j = 0; j < 4; j++)
            #pragma unroll
            for (int q = 0; q < 4; q++) { acc1[i][j][q] = 0; acc2[i][j][q] = 0; }

    // loader: 512 threads, each 1 (row, 16B-chunk) per tile
    int lr = tid >> 2;             // 0..127
    int lc = tid & 3;              // 16B chunk
    int gmr = bm + lr; if (gmr >= N_NODES) gmr = 0;
    uint32_t a_off = (uint32_t)(lane & 15) * 80 + (uint32_t)(lane >> 4) * 16;
    int bg = lane >> 3;
    uint32_t b_off = (uint32_t)((bg >> 1) * 8 + (lane & 7)) * 80 + (uint32_t)(bg & 1) * 16;

    auto load_chunk = [&](int ch, int buf) {
        int kc = ch * 64;
        uint32_t bo = sbase + buf * BUF_B;
        uint32_t dof = (uint32_t)lr * 80 + lc * 16;
        int eof = kc + lc * 16;
        cp16(bo + dof,              Ah + (size_t)gmr * KTOT + eof);
        cp16(bo + TILE_B + dof,     Al + (size_t)gmr * KTOT + eof);
        cp16(bo + 2 * TILE_B + dof, Wh + lr * KTOT + eof);
        cp16(bo + 3 * TILE_B + dof, Wl + lr * KTOT + eof);
    };

    load_chunk(0, 0);
    CP_COMMIT();

    #pragma unroll 1
    for (int ch = 0; ch < 10; ch++) {
        int buf = ch & 1;
        if (ch < 9) {
            load_chunk(ch + 1, buf ^ 1);
            CP_COMMIT();
            CP_WAIT(1);
        } else {
            CP_WAIT(0);
        }
        __syncthreads();

        uint32_t a_hi_base = sbase + buf * BUF_B;
        uint32_t a_lo_base = a_hi_base + TILE_B;
        uint32_t b_hi_base = a_hi_base + 2 * TILE_B;
        uint32_t b_lo_base = a_hi_base + 3 * TILE_B;

        #pragma unroll
        for (int kk = 0; kk < 2; kk++) {
            uint32_t kb = (uint32_t)kk * 32;   // 32 bytes = k32
            uint32_t ahi[2][4], alo[2][4];
            #pragma unroll
            for (int mf = 0; mf < 2; mf++) {
                uint32_t o = (uint32_t)(wm0 + mf * 16) * 80 + a_off + kb;
                ldm_x4(ahi[mf], a_hi_base + o);
                ldm_x4(alo[mf], a_lo_base + o);
            }
            uint32_t bhi[4][2], blo[4][2];
            #pragma unroll
            for (int pr = 0; pr < 2; pr++) {
                uint32_t o = (uint32_t)(wn0 + pr * 16) * 80 + b_off + kb;
                uint32_t th[4], tl[4];
                ldm_x4(th, b_hi_base + o);
                ldm_x4(tl, b_lo_base + o);
                bhi[pr * 2][0] = th[0]; bhi[pr * 2][1] = th[1];
                bhi[pr * 2 + 1][0] = th[2]; bhi[pr * 2 + 1][1] = th[3];
                blo[pr * 2][0] = tl[0]; blo[pr * 2][1] = tl[1];
                blo[pr * 2 + 1][0] = tl[2]; blo[pr * 2 + 1][1] = tl[3];
            }
            #pragma unroll
            for (int mf = 0; mf < 2; mf++)
                #pragma unroll
                for (int nf = 0; nf < 4; nf++) {
                    imma16832(acc1[mf][nf], ahi[mf], bhi[nf]);
                    imma16832(acc2[mf][nf], ahi[mf], blo[nf]);
                    imma16832(acc2[mf][nf], alo[mf], bhi[nf]);
                }
        }
        __syncthreads();
    }

    // epilogue: D = sA[m]*sW[n]*(16384*acc1 + 128*acc2) + bias
    int qm = lane >> 2;
    int qn = (lane & 3) * 2;
    #pragma unroll
    for (int nf = 0; nf < 4; nf++) {
        int n = wn0 + nf * 8 + qn;
        float sw0 = sW[n], sw1 = sW[n + 1];
        float b0 = bias[n], b1 = bias[n + 1];
        #pragma unroll
        for (int mf = 0; mf < 2; mf++) {
            int m0 = bm + wm0 + mf * 16 + qm;
            if (m0 < N_NODES) {
                float sa = sA[m0];
                float2 v;
                v.x = sa * sw0 * (16384.f * (float)acc1[mf][nf][0] + 128.f * (float)acc2[mf][nf][0]) + b0;
                v.y = sa * sw1 * (16384.f * (float)acc1[mf][nf][1] + 128.f * (float)acc2[mf][nf][1]) + b1;
                if (do_relu) { v.x = fmaxf(v.x, 0.f); v.y = fmaxf(v.y, 0.f); }
                *(float2*)(out + (size_t)m0 * 128 + n) = v;
            }
            if (m0 + 8 < N_NODES) {
                float sa = sA[m0 + 8];
                float2 v;
                v.x = sa * sw0 * (16384.f * (float)acc1[mf][nf][2] + 128.f * (float)acc2[mf][nf][2]) + b0;
                v.y = sa * sw1 * (16384.f * (float)acc1[mf][nf][3] + 128.f * (float)acc2[mf][nf][3]) + b1;
                if (do_relu) { v.x = fmaxf(v.x, 0.f); v.y = fmaxf(v.y, 0.f); }
                *(float2*)(out + (size_t)(m0 + 8) * 128 + n) = v;
            }
        }
    }
}

// ---------------- launch ----------------
extern "C" void kernel_launch(void* const* d_in, const int* in_sizes, int n_in,
                              void* d_out, int out_size) {
    const int*   entity       = (const int*)d_in[0];
    const int*   edge_index   = (const int*)d_in[1];
    const int*   edge_type    = (const int*)d_in[2];
    const float* edge_norm    = (const float*)d_in[3];
    // d_in[4] = DAD_rel (unused by reference output)
    const float* entity_table = (const float*)d_in[5];
    const float* relation_emb = (const float*)d_in[6];
    const float* basis1 = (const float*)d_in[7];
    const float* att1   = (const float*)d_in[8];
    const float* root1  = (const float*)d_in[9];
    const float* bias1  = (const float*)d_in[10];
    const float* basis2 = (const float*)d_in[11];
    const float* att2   = (const float*)d_in[12];
    const float* root2  = (const float*)d_in[13];
    const float* bias2  = (const float*)d_in[14];

    const int* src = edge_index;
    const int* dst = edge_index + N_EDGES;
    float* out = (float*)d_out;

    static int smem_set = 0;
    if (!smem_set) {
        cudaFuncSetAttribute(k_gemm_imma, cudaFuncAttributeMaxDynamicSharedMemorySize, SMEM_GEMM);
        smem_set = 1;
    }

    int gemm_blocks = (N_NODES + 127) / 128;   // 782

    k_zero<<<(N_NODES + 255) / 256, 256>>>();
    k_hist<<<(N_EDGES + 255) / 256, 256>>>(dst);
    k_quantw<<<256, 128>>>(basis1, root1, basis2, root2);
    k_scan<<<SCAN_BLOCKS, 1024>>>();
    k_scatter<<<(N_EDGES + 255) / 256, 256>>>(dst, src, entity, edge_type, edge_norm,
                                              (const float4*)att1, (const float4*)att2);
    k_agg0<<<AGG_BLOCKS, 256>>>((const float4*)entity_table, entity);
    k_gemm_imma<<<gemm_blocks, 512, SMEM_GEMM>>>(0, bias1, nullptr, 1);
    k_agg1<<<AGG_BLOCKS + 32, 256>>>(relation_emb, out);
    k_gemm_imma<<<gemm_blocks, 512, SMEM_GEMM>>>(1, bias2, out, 0);
}

// round 10
// speedup vs baseline: 1.1853x; 1.1853x over previous
#include <cuda_runtime.h>
#include <cuda_bf16.h>
#include <cstdint>

#define N_NODES 100000
#define N_EDGES 600000
#define DIM 128
#define KTOT 640   // 512 (4 bases x 128) + 128 (root)
#define SCAN_BLOCKS 98
#define NCHUNK 5
#define CHSZ 20000   // nodes per chunk (multiple of 8)

// ---------------- scratch (static device globals; no runtime alloc) ----------------
__device__ float g_h1[(size_t)N_NODES * DIM];
__device__ __nv_bfloat16 g_A1hi[(size_t)N_NODES * KTOT];
__device__ __nv_bfloat16 g_A1lo[(size_t)N_NODES * KTOT];
__device__ __nv_bfloat16 g_A2hi[(size_t)N_NODES * KTOT];
__device__ __nv_bfloat16 g_A2lo[(size_t)N_NODES * KTOT];
__device__ float4 g_coeff1[N_EDGES];
__device__ float4 g_coeff2[N_EDGES];
__device__ int   g_csr_src[N_EDGES];
__device__ int   g_csr_esrc[N_EDGES];
__device__ int   g_deg[N_NODES];
__device__ int   g_rowptr[N_NODES + 1];
__device__ int   g_cursor[N_NODES];
__device__ float g_invdeg[N_NODES];
__device__ unsigned long long g_scan_state[SCAN_BLOCKS];
__device__ int   g_ticket;
__device__ __nv_bfloat16 g_Whi[128 * KTOT];
__device__ __nv_bfloat16 g_Wlo[128 * KTOT];
__device__ __nv_bfloat16 g_W2hi[128 * KTOT];
__device__ __nv_bfloat16 g_W2lo[128 * KTOT];

// ---------------- helpers ----------------
__device__ __forceinline__ uint32_t smem_u32(const void* p) {
    uint32_t a;
    asm("{ .reg .u64 t; cvta.to.shared.u64 t, %1; cvt.u32.u64 %0, t; }" : "=r"(a) : "l"(p));
    return a;
}
__device__ __forceinline__ void ldm_x4(uint32_t* r, uint32_t addr) {
    asm volatile("ldmatrix.sync.aligned.m8n8.x4.shared.b16 {%0,%1,%2,%3}, [%4];"
                 : "=r"(r[0]), "=r"(r[1]), "=r"(r[2]), "=r"(r[3]) : "r"(addr));
}
__device__ __forceinline__ void mma16816(float* c, const uint32_t* a, const uint32_t* b) {
    asm volatile("mma.sync.aligned.m16n8k16.row.col.f32.bf16.bf16.f32 "
                 "{%0,%1,%2,%3}, {%4,%5,%6,%7}, {%8,%9}, {%0,%1,%2,%3};"
                 : "+f"(c[0]), "+f"(c[1]), "+f"(c[2]), "+f"(c[3])
                 : "r"(a[0]), "r"(a[1]), "r"(a[2]), "r"(a[3]), "r"(b[0]), "r"(b[1]));
}
__device__ __forceinline__ void cp16(uint32_t dst, const void* src) {
    asm volatile("cp.async.cg.shared.global [%0], [%1], 16;" :: "r"(dst), "l"(src));
}
#define CP_COMMIT() asm volatile("cp.async.commit_group;" ::: "memory")
#define CP_WAIT(N)  asm volatile("cp.async.wait_group %0;" :: "n"(N) : "memory")

__device__ __forceinline__ uint32_t pack_hi(float a, float b) {
    __nv_bfloat16 ha = __float2bfloat16(a), hb = __float2bfloat16(b);
    return (uint32_t)__bfloat16_as_ushort(ha) | ((uint32_t)__bfloat16_as_ushort(hb) << 16);
}
__device__ __forceinline__ uint32_t pack_lo(float a, float b) {
    __nv_bfloat16 ha = __float2bfloat16(a), hb = __float2bfloat16(b);
    __nv_bfloat16 la = __float2bfloat16(a - __bfloat162float(ha));
    __nv_bfloat16 lb = __float2bfloat16(b - __bfloat162float(hb));
    return (uint32_t)__bfloat16_as_ushort(la) | ((uint32_t)__bfloat16_as_ushort(lb) << 16);
}

// ---------------- 1: zero ----------------
__global__ void k_zero() {
    int i = blockIdx.x * blockDim.x + threadIdx.x;
    if (i < N_NODES) g_deg[i] = 0;
    if (i < SCAN_BLOCKS) g_scan_state[i] = 0ull;
    if (i == 0) { g_ticket = 0; g_rowptr[N_NODES] = N_EDGES; }
}

// ---------------- 2: hist + weight split (both layers) ----------------
__global__ void k_hist_prepw(const int* __restrict__ dst,
                             const float* __restrict__ basis1, const float* __restrict__ root1,
                             const float* __restrict__ basis2, const float* __restrict__ root2) {
    int i = blockIdx.x * blockDim.x + threadIdx.x;
    if (i < N_EDGES) atomicAdd(&g_deg[dst[i]], 1);
    if (i < 2 * 128 * KTOT) {
        int which = i >= 128 * KTOT;
        int idx = which ? i - 128 * KTOT : i;
        int n = idx / KTOT;
        int k = idx % KTOT;
        const float* basis = which ? basis2 : basis1;
        const float* root  = which ? root2  : root1;
        float w = (k < 512) ? basis[(size_t)k * 128 + n] : root[(size_t)(k - 512) * 128 + n];
        __nv_bfloat16 hi = __float2bfloat16(w);
        __nv_bfloat16 lo = __float2bfloat16(w - __bfloat162float(hi));
        if (which) { g_W2hi[n * KTOT + k] = hi; g_W2lo[n * KTOT + k] = lo; }
        else       { g_Whi[n * KTOT + k]  = hi; g_Wlo[n * KTOT + k]  = lo; }
    }
}

// ---------------- 3: single-pass decoupled-lookback scan ----------------
__global__ void k_scan() {
    __shared__ int sh[1024];
    __shared__ int sbid;
    __shared__ int sexcl;
    int t = threadIdx.x;
    if (t == 0) sbid = atomicAdd(&g_ticket, 1);
    __syncthreads();
    int b = sbid;
    int i = b * 1024 + t;
    int v = (i < N_NODES) ? g_deg[i] : 0;
    sh[t] = v;
    __syncthreads();
    #pragma unroll
    for (int off = 1; off < 1024; off <<= 1) {
        int x = (t >= off) ? sh[t - off] : 0;
        __syncthreads();
        sh[t] += x;
        __syncthreads();
    }
    if (t == 0) {
        int total = sh[1023];
        int excl = 0;
        if (b == 0) {
            atomicExch(&g_scan_state[0], ((unsigned long long)total << 2) | 2ull);
        } else {
            atomicExch(&g_scan_state[b], ((unsigned long long)total << 2) | 1ull);
            int j = b - 1;
            long long run = 0;
            while (true) {
                unsigned long long s = atomicAdd(&g_scan_state[j], 0ull);
                unsigned f = (unsigned)(s & 3ull);
                if (f == 0) continue;
                run += (long long)(s >> 2);
                if (f == 2) break;
                j--;
            }
            excl = (int)run;
            atomicExch(&g_scan_state[b], ((unsigned long long)(excl + total) << 2) | 2ull);
        }
        sexcl = excl;
    }
    __syncthreads();
    if (i < N_NODES) {
        int rp = sexcl + sh[t] - v;
        g_rowptr[i] = rp;
        g_cursor[i] = rp;
        g_invdeg[i] = 1.0f / fmaxf((float)v, 1.0f);
    }
}

// ---------------- 4: scatter + CSR coefficients + entity-resolved src ----------------
__global__ void k_scatter(const int* __restrict__ dst, const int* __restrict__ src,
                          const int* __restrict__ entity,
                          const int* __restrict__ etype, const float* __restrict__ enorm,
                          const float4* __restrict__ att1, const float4* __restrict__ att2) {
    int e = blockIdx.x * blockDim.x + threadIdx.x;
    if (e >= N_EDGES) return;
    int s = src[e];
    int pos = atomicAdd(&g_cursor[dst[e]], 1);
    g_csr_src[pos] = s;
    g_csr_esrc[pos] = entity[s];
    int t = etype[e];
    float n = enorm[e];
    float4 a1 = att1[t];
    float4 a2 = att2[t];
    g_coeff1[pos] = make_float4(a1.x * n, a1.y * n, a1.z * n, a1.w * n);
    g_coeff2[pos] = make_float4(a2.x * n, a2.y * n, a2.z * n, a2.w * n);
}

// ---------------- aggregation core (R4/R8-proven) ----------------
__device__ __forceinline__ void agg_node(int node, int lane,
                                         const float4* __restrict__ X4,
                                         const int* __restrict__ sidx,
                                         const float4* __restrict__ cf,
                                         float4& s0, float4& s1, float4& s2, float4& s3) {
    int beg = g_rowptr[node], end = g_rowptr[node + 1];
    int p = beg;
    for (; p + 2 <= end; p += 2) {
        float4 ca = cf[p];
        float4 cb = cf[p + 1];
        int sa = sidx[p];
        int sb = sidx[p + 1];
        float4 xa = X4[(size_t)sa * 32 + lane];
        float4 xb = X4[(size_t)sb * 32 + lane];
        s0.x = fmaf(ca.x, xa.x, s0.x); s0.y = fmaf(ca.x, xa.y, s0.y);
        s0.z = fmaf(ca.x, xa.z, s0.z); s0.w = fmaf(ca.x, xa.w, s0.w);
        s1.x = fmaf(ca.y, xa.x, s1.x); s1.y = fmaf(ca.y, xa.y, s1.y);
        s1.z = fmaf(ca.y, xa.z, s1.z); s1.w = fmaf(ca.y, xa.w, s1.w);
        s2.x = fmaf(ca.z, xa.x, s2.x); s2.y = fmaf(ca.z, xa.y, s2.y);
        s2.z = fmaf(ca.z, xa.z, s2.z); s2.w = fmaf(ca.z, xa.w, s2.w);
        s3.x = fmaf(ca.w, xa.x, s3.x); s3.y = fmaf(ca.w, xa.y, s3.y);
        s3.z = fmaf(ca.w, xa.z, s3.z); s3.w = fmaf(ca.w, xa.w, s3.w);
        s0.x = fmaf(cb.x, xb.x, s0.x); s0.y = fmaf(cb.x, xb.y, s0.y);
        s0.z = fmaf(cb.x, xb.z, s0.z); s0.w = fmaf(cb.x, xb.w, s0.w);
        s1.x = fmaf(cb.y, xb.x, s1.x); s1.y = fmaf(cb.y, xb.y, s1.y);
        s1.z = fmaf(cb.y, xb.z, s1.z); s1.w = fmaf(cb.y, xb.w, s1.w);
        s2.x = fmaf(cb.z, xb.x, s2.x); s2.y = fmaf(cb.z, xb.y, s2.y);
        s2.z = fmaf(cb.z, xb.z, s2.z); s2.w = fmaf(cb.z, xb.w, s2.w);
        s3.x = fmaf(cb.w, xb.x, s3.x); s3.y = fmaf(cb.w, xb.y, s3.y);
        s3.z = fmaf(cb.w, xb.z, s3.z); s3.w = fmaf(cb.w, xb.w, s3.w);
    }
    if (p < end) {
        float4 c = cf[p];
        int sn = sidx[p];
        float4 xv = X4[(size_t)sn * 32 + lane];
        s0.x = fmaf(c.x, xv.x, s0.x); s0.y = fmaf(c.x, xv.y, s0.y);
        s0.z = fmaf(c.x, xv.z, s0.z); s0.w = fmaf(c.x, xv.w, s0.w);
        s1.x = fmaf(c.y, xv.x, s1.x); s1.y = fmaf(c.y, xv.y, s1.y);
        s1.z = fmaf(c.y, xv.z, s1.z); s1.w = fmaf(c.y, xv.w, s1.w);
        s2.x = fmaf(c.z, xv.x, s2.x); s2.y = fmaf(c.z, xv.y, s2.y);
        s2.z = fmaf(c.z, xv.z, s2.z); s2.w = fmaf(c.z, xv.w, s2.w);
        s3.x = fmaf(c.w, xv.x, s3.x); s3.y = fmaf(c.w, xv.y, s3.y);
        s3.z = fmaf(c.w, xv.z, s3.z); s3.w = fmaf(c.w, xv.w, s3.w);
    }
}

__device__ __forceinline__ void agg_store(int node, int lane, float d,
                                          float4 s0, float4 s1, float4 s2, float4 s3,
                                          __nv_bfloat16* Ahi, __nv_bfloat16* Alo) {
    s0.x *= d; s0.y *= d; s0.z *= d; s0.w *= d;
    s1.x *= d; s1.y *= d; s1.z *= d; s1.w *= d;
    s2.x *= d; s2.y *= d; s2.z *= d; s2.w *= d;
    s3.x *= d; s3.y *= d; s3.z *= d; s3.w *= d;
    size_t base = (size_t)node * KTOT + 4 * lane;
    *(uint2*)(Ahi + base)       = make_uint2(pack_hi(s0.x, s0.y), pack_hi(s0.z, s0.w));
    *(uint2*)(Alo + base)       = make_uint2(pack_lo(s0.x, s0.y), pack_lo(s0.z, s0.w));
    *(uint2*)(Ahi + base + 128) = make_uint2(pack_hi(s1.x, s1.y), pack_hi(s1.z, s1.w));
    *(uint2*)(Alo + base + 128) = make_uint2(pack_lo(s1.x, s1.y), pack_lo(s1.z, s1.w));
    *(uint2*)(Ahi + base + 256) = make_uint2(pack_hi(s2.x, s2.y), pack_hi(s2.z, s2.w));
    *(uint2*)(Alo + base + 256) = make_uint2(pack_lo(s2.x, s2.y), pack_lo(s2.z, s2.w));
    *(uint2*)(Ahi + base + 384) = make_uint2(pack_hi(s3.x, s3.y), pack_hi(s3.z, s3.w));
    *(uint2*)(Alo + base + 384) = make_uint2(pack_lo(s3.x, s3.y), pack_lo(s3.z, s3.w));
}

// ---------------- layer-1 aggregation chunk ----------------
__global__ void k_agg0(const float4* __restrict__ tbl, const int* __restrict__ entity,
                       int nbase, int ncount) {
    int gw = nbase + ((blockIdx.x * blockDim.x + threadIdx.x) >> 5);
    int lane = threadIdx.x & 31;
    if (gw >= nbase + ncount || gw >= N_NODES) return;
    float4 s0 = make_float4(0.f, 0.f, 0.f, 0.f);
    float4 s1 = s0, s2 = s0, s3 = s0;
    agg_node(gw, lane, tbl, g_csr_esrc, g_coeff1, s0, s1, s2, s3);
    agg_store(gw, lane, g_invdeg[gw], s0, s1, s2, s3, g_A1hi, g_A1lo);
    float4 xs = tbl[(size_t)entity[gw] * 32 + lane];
    size_t a = (size_t)gw * KTOT + 512 + 4 * lane;
    *(uint2*)(g_A1hi + a) = make_uint2(pack_hi(xs.x, xs.y), pack_hi(xs.z, xs.w));
    *(uint2*)(g_A1lo + a) = make_uint2(pack_lo(xs.x, xs.y), pack_lo(xs.z, xs.w));
}

// ---------------- layer-2 aggregation chunk (+ relation_emb copy tail on first chunk) ----------------
__global__ void k_agg1(const float* __restrict__ rel, float* __restrict__ out,
                       int nbase, int ncount, int agg_blocks) {
    if (blockIdx.x >= (unsigned)agg_blocks) {
        int i = (blockIdx.x - agg_blocks) * 256 + threadIdx.x;
        for (; i < 500 * 128; i += 32 * 256)
            out[(size_t)N_NODES * 128 + i] = rel[i];
        return;
    }
    int gw = nbase + ((blockIdx.x * blockDim.x + threadIdx.x) >> 5);
    int lane = threadIdx.x & 31;
    if (gw >= nbase + ncount || gw >= N_NODES) return;
    float4 s0 = make_float4(0.f, 0.f, 0.f, 0.f);
    float4 s1 = s0, s2 = s0, s3 = s0;
    agg_node(gw, lane, (const float4*)g_h1, g_csr_src, g_coeff2, s0, s1, s2, s3);
    agg_store(gw, lane, g_invdeg[gw], s0, s1, s2, s3, g_A2hi, g_A2lo);
    // A2 root columns written by layer-1 GEMM epilogue.
}

// ---------------- HMMA GEMM chunk, cp.async double-buffered (R8-proven core) ----------------
#define TILE_B 10240
#define BUF_B  (4 * TILE_B)
#define SMEM_GEMM (2 * BUF_B)   // 81920 -> 2 CTAs/SM

__global__ __launch_bounds__(256) void k_gemm_mma(
    int layer, const float* __restrict__ bias, float* __restrict__ out_param, int do_relu,
    int nbase, int nlim)
{
    extern __shared__ char smem[];
    uint32_t sbase = smem_u32(smem);
    const __nv_bfloat16* Ahi = (layer == 0) ? g_A1hi : g_A2hi;
    const __nv_bfloat16* Alo = (layer == 0) ? g_A1lo : g_A2lo;
    const __nv_bfloat16* Whi = (layer == 0) ? g_Whi : g_W2hi;
    const __nv_bfloat16* Wlo = (layer == 0) ? g_Wlo : g_W2lo;
    float* out = (layer == 0) ? g_h1 : out_param;

    int tid = threadIdx.x;
    int wid = tid >> 5;
    int lane = tid & 31;
    int bm = nbase + blockIdx.x * 128;
    int wm0 = (wid >> 2) * 64;
    int wn0 = (wid & 3) * 32;

    float acc[4][4][4];
    #pragma unroll
    for (int i = 0; i < 4; i++)
        #pragma unroll
        for (int j = 0; j < 4; j++)
            #pragma unroll
            for (int q = 0; q < 4; q++) acc[i][j][q] = 0.f;

    int lr = tid >> 1;
    int lc0 = (tid & 1) * 2;
    int gmr = bm + lr; if (gmr >= nlim) gmr = nbase;
    uint32_t a_off = (uint32_t)(lane & 15) * 80 + (uint32_t)(lane >> 4) * 16;
    int bg = lane >> 3;
    uint32_t b_off = (uint32_t)((bg >> 1) * 8 + (lane & 7)) * 80 + (uint32_t)(bg & 1) * 16;

    auto load_chunk = [&](int ch, int buf) {
        int kc = ch * 32;
        uint32_t bo = sbase + buf * BUF_B;
        uint32_t drow = (uint32_t)lr * 80;
        #pragma unroll
        for (int c = 0; c < 2; c++) {
            int cc = lc0 + c;
            uint32_t dof = drow + cc * 16;
            int eof = kc + cc * 8;
            cp16(bo + dof,              Ahi + (size_t)gmr * KTOT + eof);
            cp16(bo + TILE_B + dof,     Alo + (size_t)gmr * KTOT + eof);
            cp16(bo + 2 * TILE_B + dof, Whi + lr * KTOT + eof);
            cp16(bo + 3 * TILE_B + dof, Wlo + lr * KTOT + eof);
        }
    };

    load_chunk(0, 0);
    CP_COMMIT();

    #pragma unroll 1
    for (int ch = 0; ch < 20; ch++) {
        int buf = ch & 1;
        if (ch < 19) {
            load_chunk(ch + 1, buf ^ 1);
            CP_COMMIT();
            CP_WAIT(1);
        } else {
            CP_WAIT(0);
        }
        __syncthreads();

        uint32_t a_hi_base = sbase + buf * BUF_B;
        uint32_t a_lo_base = a_hi_base + TILE_B;
        uint32_t b_hi_base = a_hi_base + 2 * TILE_B;
        uint32_t b_lo_base = a_hi_base + 3 * TILE_B;

        #pragma unroll
        for (int kk = 0; kk < 2; kk++) {
            uint32_t kb = (uint32_t)kk * 32;
            uint32_t ahi[4][4], alo[4][4];
            #pragma unroll
            for (int mf = 0; mf < 4; mf++) {
                uint32_t o = (uint32_t)(wm0 + mf * 16) * 80 + a_off + kb;
                ldm_x4(ahi[mf], a_hi_base + o);
                ldm_x4(alo[mf], a_lo_base + o);
            }
            uint32_t bhi[4][2], blo[4][2];
            #pragma unroll
            for (int pr = 0; pr < 2; pr++) {
                uint32_t o = (uint32_t)(wn0 + pr * 16) * 80 + b_off + kb;
                uint32_t th[4], tl[4];
                ldm_x4(th, b_hi_base + o);
                ldm_x4(tl, b_lo_base + o);
                bhi[pr * 2][0] = th[0]; bhi[pr * 2][1] = th[1];
                bhi[pr * 2 + 1][0] = th[2]; bhi[pr * 2 + 1][1] = th[3];
                blo[pr * 2][0] = tl[0]; blo[pr * 2][1] = tl[1];
                blo[pr * 2 + 1][0] = tl[2]; blo[pr * 2 + 1][1] = tl[3];
            }
            #pragma unroll
            for (int mf = 0; mf < 4; mf++)
                #pragma unroll
                for (int nf = 0; nf < 4; nf++) {
                    mma16816(acc[mf][nf], ahi[mf], bhi[nf]);
                    mma16816(acc[mf][nf], ahi[mf], blo[nf]);
                    mma16816(acc[mf][nf], alo[mf], bhi[nf]);
                }
        }
        __syncthreads();
    }

    int qm = lane >> 2;
    int qn = (lane & 3) * 2;
    #pragma unroll
    for (int nf = 0; nf < 4; nf++) {
        int n = wn0 + nf * 8 + qn;
        float b0 = bias[n], b1 = bias[n + 1];
        #pragma unroll
        for (int mf = 0; mf < 4; mf++) {
            int m0 = bm + wm0 + mf * 16 + qm;
            float2 lo = make_float2(acc[mf][nf][0] + b0, acc[mf][nf][1] + b1);
            float2 hi = make_float2(acc[mf][nf][2] + b0, acc[mf][nf][3] + b1);
            if (do_relu) {
                lo.x = fmaxf(lo.x, 0.f); lo.y = fmaxf(lo.y, 0.f);
                hi.x = fmaxf(hi.x, 0.f); hi.y = fmaxf(hi.y, 0.f);
            }
            if (m0 < nlim) {
                *(float2*)(out + (size_t)m0 * 128 + n) = lo;
                if (layer == 0) {
                    size_t a = (size_t)m0 * KTOT + 512 + n;
                    *(uint32_t*)(g_A2hi + a) = pack_hi(lo.x, lo.y);
                    *(uint32_t*)(g_A2lo + a) = pack_lo(lo.x, lo.y);
                }
            }
            if (m0 + 8 < nlim) {
                *(float2*)(out + (size_t)(m0 + 8) * 128 + n) = hi;
                if (layer == 0) {
                    size_t a = (size_t)(m0 + 8) * KTOT + 512 + n;
                    *(uint32_t*)(g_A2hi + a) = pack_hi(hi.x, hi.y);
                    *(uint32_t*)(g_A2lo + a) = pack_lo(hi.x, hi.y);
                }
            }
        }
    }
}

// ---------------- launch ----------------
extern "C" void kernel_launch(void* const* d_in, const int* in_sizes, int n_in,
                              void* d_out, int out_size) {
    const int*   entity       = (const int*)d_in[0];
    const int*   edge_index   = (const int*)d_in[1];
    const int*   edge_type    = (const int*)d_in[2];
    const float* edge_norm    = (const float*)d_in[3];
    // d_in[4] = DAD_rel (unused by reference output)
    const float* entity_table = (const float*)d_in[5];
    const float* relation_emb = (const float*)d_in[6];
    const float* basis1 = (const float*)d_in[7];
    const float* att1   = (const float*)d_in[8];
    const float* root1  = (const float*)d_in[9];
    const float* bias1  = (const float*)d_in[10];
    const float* basis2 = (const float*)d_in[11];
    const float* att2   = (const float*)d_in[12];
    const float* root2  = (const float*)d_in[13];
    const float* bias2  = (const float*)d_in[14];

    const int* src = edge_index;
    const int* dst = edge_index + N_EDGES;
    float* out = (float*)d_out;

    static int smem_set = 0;
    if (!smem_set) {
        cudaFuncSetAttribute(k_gemm_mma, cudaFuncAttributeMaxDynamicSharedMemorySize, SMEM_GEMM);
        smem_set = 1;
    }

    // pre-CSR
    k_zero<<<(N_NODES + 255) / 256, 256>>>();
    k_hist_prepw<<<(N_EDGES + 255) / 256, 256>>>(dst, basis1, root1, basis2, root2);
    k_scan<<<SCAN_BLOCKS, 1024>>>();
    k_scatter<<<(N_EDGES + 255) / 256, 256>>>(dst, src, entity, edge_type, edge_norm,
                                              (const float4*)att1, (const float4*)att2);

    // layer 1: chunked agg -> gemm (A1 chunk stays L2-resident)
    for (int c = 0; c < NCHUNK; c++) {
        int nb = c * CHSZ;
        int nc = (nb + CHSZ <= N_NODES) ? CHSZ : (N_NODES - nb);
        int agg_blocks = (nc + 7) / 8;
        int gemm_blocks = (nc + 127) / 128;
        k_agg0<<<agg_blocks, 256>>>((const float4*)entity_table, entity, nb, nc);
        k_gemm_mma<<<gemm_blocks, 256, SMEM_GEMM>>>(0, bias1, nullptr, 1, nb, nb + nc);
    }

    // layer 2: chunked agg -> gemm; first agg also copies relation_emb
    for (int c = 0; c < NCHUNK; c++) {
        int nb = c * CHSZ;
        int nc = (nb + CHSZ <= N_NODES) ? CHSZ : (N_NODES - nb);
        int agg_blocks = (nc + 7) / 8;
        int gemm_blocks = (nc + 127) / 128;
        int extra = (c == 0) ? 32 : 0;
        k_agg1<<<agg_blocks + extra, 256>>>(relation_emb, out, nb, nc, agg_blocks);
        k_gemm_mma<<<gemm_blocks, 256, SMEM_GEMM>>>(1, bias2, out, 0, nb, nb + nc);
    }
}

// round 11
// speedup vs baseline: 1.8547x; 1.5648x over previous
#include <cuda_runtime.h>
#include <cuda_bf16.h>
#include <cstdint>

#define N_NODES 100000
#define N_EDGES 600000
#define DIM 128
#define KTOT 640   // 512 (4 bases x 128) + 128 (root)
#define SCAN_BLOCKS 98
#define AGG_BLOCKS 12500

// ---------------- scratch (static device globals; zero-initialized at load,
// re-zeroed by cleanup blocks at the end of each call) ----------------
__device__ float g_h1[(size_t)N_NODES * DIM];
__device__ __nv_bfloat16 g_A1hi[(size_t)N_NODES * KTOT];
__device__ __nv_bfloat16 g_A1lo[(size_t)N_NODES * KTOT];
__device__ __nv_bfloat16 g_A2hi[(size_t)N_NODES * KTOT];
__device__ __nv_bfloat16 g_A2lo[(size_t)N_NODES * KTOT];
__device__ float4 g_coeff1[N_EDGES];
__device__ float4 g_coeff2[N_EDGES];
__device__ int   g_csr_src[N_EDGES];
__device__ int   g_csr_esrc[N_EDGES];
__device__ int   g_deg[N_NODES];                          // must be 0 at call entry
__device__ int   g_rowptr[N_NODES + 1];
__device__ int   g_cursor[N_NODES];
__device__ float g_invdeg[N_NODES];
__device__ unsigned long long g_scan_state[SCAN_BLOCKS];  // must be 0 at call entry
__device__ int   g_ticket;                                // must be 0 at call entry
__device__ __nv_bfloat16 g_Whi[128 * KTOT];
__device__ __nv_bfloat16 g_Wlo[128 * KTOT];
__device__ __nv_bfloat16 g_W2hi[128 * KTOT];
__device__ __nv_bfloat16 g_W2lo[128 * KTOT];

// ---------------- helpers ----------------
__device__ __forceinline__ uint32_t smem_u32(const void* p) {
    uint32_t a;
    asm("{ .reg .u64 t; cvta.to.shared.u64 t, %1; cvt.u32.u64 %0, t; }" : "=r"(a) : "l"(p));
    return a;
}
__device__ __forceinline__ void ldm_x4(uint32_t* r, uint32_t addr) {
    asm volatile("ldmatrix.sync.aligned.m8n8.x4.shared.b16 {%0,%1,%2,%3}, [%4];"
                 : "=r"(r[0]), "=r"(r[1]), "=r"(r[2]), "=r"(r[3]) : "r"(addr));
}
__device__ __forceinline__ void mma16816(float* c, const uint32_t* a, const uint32_t* b) {
    asm volatile("mma.sync.aligned.m16n8k16.row.col.f32.bf16.bf16.f32 "
                 "{%0,%1,%2,%3}, {%4,%5,%6,%7}, {%8,%9}, {%0,%1,%2,%3};"
                 : "+f"(c[0]), "+f"(c[1]), "+f"(c[2]), "+f"(c[3])
                 : "r"(a[0]), "r"(a[1]), "r"(a[2]), "r"(a[3]), "r"(b[0]), "r"(b[1]));
}
__device__ __forceinline__ void cp16(uint32_t dst, const void* src) {
    asm volatile("cp.async.cg.shared.global [%0], [%1], 16;" :: "r"(dst), "l"(src));
}
#define CP_COMMIT() asm volatile("cp.async.commit_group;" ::: "memory")
#define CP_WAIT(N)  asm volatile("cp.async.wait_group %0;" :: "n"(N) : "memory")

__device__ __forceinline__ uint32_t pack_hi(float a, float b) {
    __nv_bfloat16 ha = __float2bfloat16(a), hb = __float2bfloat16(b);
    return (uint32_t)__bfloat16_as_ushort(ha) | ((uint32_t)__bfloat16_as_ushort(hb) << 16);
}
__device__ __forceinline__ uint32_t pack_lo(float a, float b) {
    __nv_bfloat16 ha = __float2bfloat16(a), hb = __float2bfloat16(b);
    __nv_bfloat16 la = __float2bfloat16(a - __bfloat162float(ha));
    __nv_bfloat16 lb = __float2bfloat16(b - __bfloat162float(hb));
    return (uint32_t)__bfloat16_as_ushort(la) | ((uint32_t)__bfloat16_as_ushort(lb) << 16);
}

// ---------------- 1: hist + weight split (deg arrives zeroed) ----------------
__global__ void k_hist_prepw(const int* __restrict__ dst,
                             const float* __restrict__ basis1, const float* __restrict__ root1,
                             const float* __restrict__ basis2, const float* __restrict__ root2) {
    int i = blockIdx.x * blockDim.x + threadIdx.x;
    if (i == 0) g_rowptr[N_NODES] = N_EDGES;
    if (i < N_EDGES) atomicAdd(&g_deg[dst[i]], 1);
    if (i < 2 * 128 * KTOT) {
        int which = i >= 128 * KTOT;
        int idx = which ? i - 128 * KTOT : i;
        int n = idx / KTOT;
        int k = idx % KTOT;
        const float* basis = which ? basis2 : basis1;
        const float* root  = which ? root2  : root1;
        float w = (k < 512) ? basis[(size_t)k * 128 + n] : root[(size_t)(k - 512) * 128 + n];
        __nv_bfloat16 hi = __float2bfloat16(w);
        __nv_bfloat16 lo = __float2bfloat16(w - __bfloat162float(hi));
        if (which) { g_W2hi[n * KTOT + k] = hi; g_W2lo[n * KTOT + k] = lo; }
        else       { g_Whi[n * KTOT + k]  = hi; g_Wlo[n * KTOT + k]  = lo; }
    }
}

// ---------------- 2: single-pass decoupled-lookback scan (state arrives zeroed) ----------------
__global__ void k_scan() {
    __shared__ int sh[1024];
    __shared__ int sbid;
    __shared__ int sexcl;
    int t = threadIdx.x;
    if (t == 0) sbid = atomicAdd(&g_ticket, 1);
    __syncthreads();
    int b = sbid;
    int i = b * 1024 + t;
    int v = (i < N_NODES) ? g_deg[i] : 0;
    sh[t] = v;
    __syncthreads();
    #pragma unroll
    for (int off = 1; off < 1024; off <<= 1) {
        int x = (t >= off) ? sh[t - off] : 0;
        __syncthreads();
        sh[t] += x;
        __syncthreads();
    }
    if (t == 0) {
        int total = sh[1023];
        int excl = 0;
        if (b == 0) {
            atomicExch(&g_scan_state[0], ((unsigned long long)total << 2) | 2ull);
        } else {
            atomicExch(&g_scan_state[b], ((unsigned long long)total << 2) | 1ull);
            int j = b - 1;
            long long run = 0;
            while (true) {
                unsigned long long s = atomicAdd(&g_scan_state[j], 0ull);
                unsigned f = (unsigned)(s & 3ull);
                if (f == 0) continue;
                run += (long long)(s >> 2);
                if (f == 2) break;
                j--;
            }
            excl = (int)run;
            atomicExch(&g_scan_state[b], ((unsigned long long)(excl + total) << 2) | 2ull);
        }
        sexcl = excl;
    }
    __syncthreads();
    if (i < N_NODES) {
        int rp = sexcl + sh[t] - v;
        g_rowptr[i] = rp;
        g_cursor[i] = rp;
        g_invdeg[i] = 1.0f / fmaxf((float)v, 1.0f);
    }
}

// ---------------- 3: scatter + CSR coefficients + entity-resolved src ----------------
__global__ void k_scatter(const int* __restrict__ dst, const int* __restrict__ src,
                          const int* __restrict__ entity,
                          const int* __restrict__ etype, const float* __restrict__ enorm,
                          const float4* __restrict__ att1, const float4* __restrict__ att2) {
    int e = blockIdx.x * blockDim.x + threadIdx.x;
    if (e >= N_EDGES) return;
    int s = src[e];
    int pos = atomicAdd(&g_cursor[dst[e]], 1);
    g_csr_src[pos] = s;
    g_csr_esrc[pos] = entity[s];
    int t = etype[e];
    float n = enorm[e];
    float4 a1 = att1[t];
    float4 a2 = att2[t];
    g_coeff1[pos] = make_float4(a1.x * n, a1.y * n, a1.z * n, a1.w * n);
    g_coeff2[pos] = make_float4(a2.x * n, a2.y * n, a2.z * n, a2.w * n);
}

// ---------------- aggregation core (R4/R8-proven) ----------------
__device__ __forceinline__ void agg_node(int node, int lane,
                                         const float4* __restrict__ X4,
                                         const int* __restrict__ sidx,
                                         const float4* __restrict__ cf,
                                         float4& s0, float4& s1, float4& s2, float4& s3) {
    int beg = g_rowptr[node], end = g_rowptr[node + 1];
    int p = beg;
    for (; p + 2 <= end; p += 2) {
        float4 ca = cf[p];
        float4 cb = cf[p + 1];
        int sa = sidx[p];
        int sb = sidx[p + 1];
        float4 xa = X4[(size_t)sa * 32 + lane];
        float4 xb = X4[(size_t)sb * 32 + lane];
        s0.x = fmaf(ca.x, xa.x, s0.x); s0.y = fmaf(ca.x, xa.y, s0.y);
        s0.z = fmaf(ca.x, xa.z, s0.z); s0.w = fmaf(ca.x, xa.w, s0.w);
        s1.x = fmaf(ca.y, xa.x, s1.x); s1.y = fmaf(ca.y, xa.y, s1.y);
        s1.z = fmaf(ca.y, xa.z, s1.z); s1.w = fmaf(ca.y, xa.w, s1.w);
        s2.x = fmaf(ca.z, xa.x, s2.x); s2.y = fmaf(ca.z, xa.y, s2.y);
        s2.z = fmaf(ca.z, xa.z, s2.z); s2.w = fmaf(ca.z, xa.w, s2.w);
        s3.x = fmaf(ca.w, xa.x, s3.x); s3.y = fmaf(ca.w, xa.y, s3.y);
        s3.z = fmaf(ca.w, xa.z, s3.z); s3.w = fmaf(ca.w, xa.w, s3.w);
        s0.x = fmaf(cb.x, xb.x, s0.x); s0.y = fmaf(cb.x, xb.y, s0.y);
        s0.z = fmaf(cb.x, xb.z, s0.z); s0.w = fmaf(cb.x, xb.w, s0.w);
        s1.x = fmaf(cb.y, xb.x, s1.x); s1.y = fmaf(cb.y, xb.y, s1.y);
        s1.z = fmaf(cb.y, xb.z, s1.z); s1.w = fmaf(cb.y, xb.w, s1.w);
        s2.x = fmaf(cb.z, xb.x, s2.x); s2.y = fmaf(cb.z, xb.y, s2.y);
        s2.z = fmaf(cb.z, xb.z, s2.z); s2.w = fmaf(cb.z, xb.w, s2.w);
        s3.x = fmaf(cb.w, xb.x, s3.x); s3.y = fmaf(cb.w, xb.y, s3.y);
        s3.z = fmaf(cb.w, xb.z, s3.z); s3.w = fmaf(cb.w, xb.w, s3.w);
    }
    if (p < end) {
        float4 c = cf[p];
        int sn = sidx[p];
        float4 xv = X4[(size_t)sn * 32 + lane];
        s0.x = fmaf(c.x, xv.x, s0.x); s0.y = fmaf(c.x, xv.y, s0.y);
        s0.z = fmaf(c.x, xv.z, s0.z); s0.w = fmaf(c.x, xv.w, s0.w);
        s1.x = fmaf(c.y, xv.x, s1.x); s1.y = fmaf(c.y, xv.y, s1.y);
        s1.z = fmaf(c.y, xv.z, s1.z); s1.w = fmaf(c.y, xv.w, s1.w);
        s2.x = fmaf(c.z, xv.x, s2.x); s2.y = fmaf(c.z, xv.y, s2.y);
        s2.z = fmaf(c.z, xv.z, s2.z); s2.w = fmaf(c.z, xv.w, s2.w);
        s3.x = fmaf(c.w, xv.x, s3.x); s3.y = fmaf(c.w, xv.y, s3.y);
        s3.z = fmaf(c.w, xv.z, s3.z); s3.w = fmaf(c.w, xv.w, s3.w);
    }
}

__device__ __forceinline__ void agg_store(int node, int lane, float d,
                                          float4 s0, float4 s1, float4 s2, float4 s3,
                                          __nv_bfloat16* Ahi, __nv_bfloat16* Alo) {
    s0.x *= d; s0.y *= d; s0.z *= d; s0.w *= d;
    s1.x *= d; s1.y *= d; s1.z *= d; s1.w *= d;
    s2.x *= d; s2.y *= d; s2.z *= d; s2.w *= d;
    s3.x *= d; s3.y *= d; s3.z *= d; s3.w *= d;
    size_t base = (size_t)node * KTOT + 4 * lane;
    *(uint2*)(Ahi + base)       = make_uint2(pack_hi(s0.x, s0.y), pack_hi(s0.z, s0.w));
    *(uint2*)(Alo + base)       = make_uint2(pack_lo(s0.x, s0.y), pack_lo(s0.z, s0.w));
    *(uint2*)(Ahi + base + 128) = make_uint2(pack_hi(s1.x, s1.y), pack_hi(s1.z, s1.w));
    *(uint2*)(Alo + base + 128) = make_uint2(pack_lo(s1.x, s1.y), pack_lo(s1.z, s1.w));
    *(uint2*)(Ahi + base + 256) = make_uint2(pack_hi(s2.x, s2.y), pack_hi(s2.z, s2.w));
    *(uint2*)(Alo + base + 256) = make_uint2(pack_lo(s2.x, s2.y), pack_lo(s2.z, s2.w));
    *(uint2*)(Ahi + base + 384) = make_uint2(pack_hi(s3.x, s3.y), pack_hi(s3.z, s3.w));
    *(uint2*)(Alo + base + 384) = make_uint2(pack_lo(s3.x, s3.y), pack_lo(s3.z, s3.w));
}

// ---------------- 4: layer-1 aggregation (PROFILED SLOT) ----------------
__global__ void k_agg0(const float4* __restrict__ tbl, const int* __restrict__ entity) {
    int gw = (blockIdx.x * blockDim.x + threadIdx.x) >> 5;
    int lane = threadIdx.x & 31;
    if (gw >= N_NODES) return;
    float4 s0 = make_float4(0.f, 0.f, 0.f, 0.f);
    float4 s1 = s0, s2 = s0, s3 = s0;
    agg_node(gw, lane, tbl, g_csr_esrc, g_coeff1, s0, s1, s2, s3);
    agg_store(gw, lane, g_invdeg[gw], s0, s1, s2, s3, g_A1hi, g_A1lo);
    float4 xs = tbl[(size_t)entity[gw] * 32 + lane];
    size_t a = (size_t)gw * KTOT + 512 + 4 * lane;
    *(uint2*)(g_A1hi + a) = make_uint2(pack_hi(xs.x, xs.y), pack_hi(xs.z, xs.w));
    *(uint2*)(g_A1lo + a) = make_uint2(pack_lo(xs.x, xs.y), pack_lo(xs.z, xs.w));
}

// ---------------- 6: layer-2 aggregation + relation_emb copy + state cleanup ----------------
#define REL_BLOCKS 32
#define CLEAN_BLOCKS 391   // ceil(100000/256)
__global__ void k_agg1(const float* __restrict__ rel, float* __restrict__ out) {
    if (blockIdx.x >= AGG_BLOCKS + REL_BLOCKS) {
        // cleanup: restore zero-state for next replay (deg, scan_state, ticket)
        int i = (blockIdx.x - AGG_BLOCKS - REL_BLOCKS) * 256 + threadIdx.x;
        if (i < N_NODES) g_deg[i] = 0;
        if (i < SCAN_BLOCKS) g_scan_state[i] = 0ull;
        if (i == 0) g_ticket = 0;
        return;
    }
    if (blockIdx.x >= AGG_BLOCKS) {
        int i = (blockIdx.x - AGG_BLOCKS) * 256 + threadIdx.x;
        for (; i < 500 * 128; i += REL_BLOCKS * 256)
            out[(size_t)N_NODES * 128 + i] = rel[i];
        return;
    }
    int gw = (blockIdx.x * blockDim.x + threadIdx.x) >> 5;
    int lane = threadIdx.x & 31;
    if (gw >= N_NODES) return;
    float4 s0 = make_float4(0.f, 0.f, 0.f, 0.f);
    float4 s1 = s0, s2 = s0, s3 = s0;
    agg_node(gw, lane, (const float4*)g_h1, g_csr_src, g_coeff2, s0, s1, s2, s3);
    agg_store(gw, lane, g_invdeg[gw], s0, s1, s2, s3, g_A2hi, g_A2lo);
    // A2 root columns written by layer-1 GEMM epilogue.
}

// ---------------- 5/7: HMMA GEMM, cp.async double-buffered (R8-proven) ----------------
#define TILE_B 10240
#define BUF_B  (4 * TILE_B)
#define SMEM_GEMM (2 * BUF_B)   // 81920 -> 2 CTAs/SM

__global__ __launch_bounds__(256) void k_gemm_mma(
    int layer, const float* __restrict__ bias, float* __restrict__ out_param, int do_relu)
{
    extern __shared__ char smem[];
    uint32_t sbase = smem_u32(smem);
    const __nv_bfloat16* Ahi = (layer == 0) ? g_A1hi : g_A2hi;
    const __nv_bfloat16* Alo = (layer == 0) ? g_A1lo : g_A2lo;
    const __nv_bfloat16* Whi = (layer == 0) ? g_Whi : g_W2hi;
    const __nv_bfloat16* Wlo = (layer == 0) ? g_Wlo : g_W2lo;
    float* out = (layer == 0) ? g_h1 : out_param;

    int tid = threadIdx.x;
    int wid = tid >> 5;
    int lane = tid & 31;
    int bm = blockIdx.x * 128;
    int wm0 = (wid >> 2) * 64;
    int wn0 = (wid & 3) * 32;

    float acc[4][4][4];
    #pragma unroll
    for (int i = 0; i < 4; i++)
        #pragma unroll
        for (int j = 0; j < 4; j++)
            #pragma unroll
            for (int q = 0; q < 4; q++) acc[i][j][q] = 0.f;

    int lr = tid >> 1;
    int lc0 = (tid & 1) * 2;
    int gmr = bm + lr; if (gmr >= N_NODES) gmr = 0;
    uint32_t a_off = (uint32_t)(lane & 15) * 80 + (uint32_t)(lane >> 4) * 16;
    int bg = lane >> 3;
    uint32_t b_off = (uint32_t)((bg >> 1) * 8 + (lane & 7)) * 80 + (uint32_t)(bg & 1) * 16;

    auto load_chunk = [&](int ch, int buf) {
        int kc = ch * 32;
        uint32_t bo = sbase + buf * BUF_B;
        uint32_t drow = (uint32_t)lr * 80;
        #pragma unroll
        for (int c = 0; c < 2; c++) {
            int cc = lc0 + c;
            uint32_t dof = drow + cc * 16;
            int eof = kc + cc * 8;
            cp16(bo + dof,              Ahi + (size_t)gmr * KTOT + eof);
            cp16(bo + TILE_B + dof,     Alo + (size_t)gmr * KTOT + eof);
            cp16(bo + 2 * TILE_B + dof, Whi + lr * KTOT + eof);
            cp16(bo + 3 * TILE_B + dof, Wlo + lr * KTOT + eof);
        }
    };

    load_chunk(0, 0);
    CP_COMMIT();

    #pragma unroll 1
    for (int ch = 0; ch < 20; ch++) {
        int buf = ch & 1;
        if (ch < 19) {
            load_chunk(ch + 1, buf ^ 1);
            CP_COMMIT();
            CP_WAIT(1);
        } else {
            CP_WAIT(0);
        }
        __syncthreads();

        uint32_t a_hi_base = sbase + buf * BUF_B;
        uint32_t a_lo_base = a_hi_base + TILE_B;
        uint32_t b_hi_base = a_hi_base + 2 * TILE_B;
        uint32_t b_lo_base = a_hi_base + 3 * TILE_B;

        #pragma unroll
        for (int kk = 0; kk < 2; kk++) {
            uint32_t kb = (uint32_t)kk * 32;
            uint32_t ahi[4][4], alo[4][4];
            #pragma unroll
            for (int mf = 0; mf < 4; mf++) {
                uint32_t o = (uint32_t)(wm0 + mf * 16) * 80 + a_off + kb;
                ldm_x4(ahi[mf], a_hi_base + o);
                ldm_x4(alo[mf], a_lo_base + o);
            }
            uint32_t bhi[4][2], blo[4][2];
            #pragma unroll
            for (int pr = 0; pr < 2; pr++) {
                uint32_t o = (uint32_t)(wn0 + pr * 16) * 80 + b_off + kb;
                uint32_t th[4], tl[4];
                ldm_x4(th, b_hi_base + o);
                ldm_x4(tl, b_lo_base + o);
                bhi[pr * 2][0] = th[0]; bhi[pr * 2][1] = th[1];
                bhi[pr * 2 + 1][0] = th[2]; bhi[pr * 2 + 1][1] = th[3];
                blo[pr * 2][0] = tl[0]; blo[pr * 2][1] = tl[1];
                blo[pr * 2 + 1][0] = tl[2]; blo[pr * 2 + 1][1] = tl[3];
            }
            #pragma unroll
            for (int mf = 0; mf < 4; mf++)
                #pragma unroll
                for (int nf = 0; nf < 4; nf++) {
                    mma16816(acc[mf][nf], ahi[mf], bhi[nf]);
                    mma16816(acc[mf][nf], ahi[mf], blo[nf]);
                    mma16816(acc[mf][nf], alo[mf], bhi[nf]);
                }
        }
        __syncthreads();
    }

    int qm = lane >> 2;
    int qn = (lane & 3) * 2;
    #pragma unroll
    for (int nf = 0; nf < 4; nf++) {
        int n = wn0 + nf * 8 + qn;
        float b0 = bias[n], b1 = bias[n + 1];
        #pragma unroll
        for (int mf = 0; mf < 4; mf++) {
            int m0 = bm + wm0 + mf * 16 + qm;
            float2 lo = make_float2(acc[mf][nf][0] + b0, acc[mf][nf][1] + b1);
            float2 hi = make_float2(acc[mf][nf][2] + b0, acc[mf][nf][3] + b1);
            if (do_relu) {
                lo.x = fmaxf(lo.x, 0.f); lo.y = fmaxf(lo.y, 0.f);
                hi.x = fmaxf(hi.x, 0.f); hi.y = fmaxf(hi.y, 0.f);
            }
            if (m0 < N_NODES) {
                *(float2*)(out + (size_t)m0 * 128 + n) = lo;
                if (layer == 0) {
                    size_t a = (size_t)m0 * KTOT + 512 + n;
                    *(uint32_t*)(g_A2hi + a) = pack_hi(lo.x, lo.y);
                    *(uint32_t*)(g_A2lo + a) = pack_lo(lo.x, lo.y);
                }
            }
            if (m0 + 8 < N_NODES) {
                *(float2*)(out + (size_t)(m0 + 8) * 128 + n) = hi;
                if (layer == 0) {
                    size_t a = (size_t)(m0 + 8) * KTOT + 512 + n;
                    *(uint32_t*)(g_A2hi + a) = pack_hi(hi.x, hi.y);
                    *(uint32_t*)(g_A2lo + a) = pack_lo(hi.x, hi.y);
                }
            }
        }
    }
}

// ---------------- launch ----------------
extern "C" void kernel_launch(void* const* d_in, const int* in_sizes, int n_in,
                              void* d_out, int out_size) {
    const int*   entity       = (const int*)d_in[0];
    const int*   edge_index   = (const int*)d_in[1];
    const int*   edge_type    = (const int*)d_in[2];
    const float* edge_norm    = (const float*)d_in[3];
    // d_in[4] = DAD_rel (unused by reference output)
    const float* entity_table = (const float*)d_in[5];
    const float* relation_emb = (const float*)d_in[6];
    const float* basis1 = (const float*)d_in[7];
    const float* att1   = (const float*)d_in[8];
    const float* root1  = (const float*)d_in[9];
    const float* bias1  = (const float*)d_in[10];
    const float* basis2 = (const float*)d_in[11];
    const float* att2   = (const float*)d_in[12];
    const float* root2  = (const float*)d_in[13];
    const float* bias2  = (const float*)d_in[14];

    const int* src = edge_index;
    const int* dst = edge_index + N_EDGES;
    float* out = (float*)d_out;

    static int smem_set = 0;
    if (!smem_set) {
        cudaFuncSetAttribute(k_gemm_mma, cudaFuncAttributeMaxDynamicSharedMemorySize, SMEM_GEMM);
        smem_set = 1;
    }

    int gemm_blocks = (N_NODES + 127) / 128;   // 782

    // 1: histogram + weight split (deg/scan_state/ticket arrive zeroed)
    k_hist_prepw<<<(N_EDGES + 255) / 256, 256>>>(dst, basis1, root1, basis2, root2);
    // 2: single-pass scan
    k_scan<<<SCAN_BLOCKS, 1024>>>();
    // 3: scatter
    k_scatter<<<(N_EDGES + 255) / 256, 256>>>(dst, src, entity, edge_type, edge_norm,
                                              (const float4*)att1, (const float4*)att2);
    // 4: layer-1 aggregation  [profiled slot]
    k_agg0<<<AGG_BLOCKS, 256>>>((const float4*)entity_table, entity);
    // 5: layer-1 GEMM (relu) -> h1 + A2 root cols
    k_gemm_mma<<<gemm_blocks, 256, SMEM_GEMM>>>(0, bias1, nullptr, 1);
    // 6: layer-2 aggregation + relation_emb + state cleanup for next replay
    k_agg1<<<AGG_BLOCKS + REL_BLOCKS + CLEAN_BLOCKS, 256>>>(relation_emb, out);
    // 7: layer-2 GEMM (no relu) -> d_out
    k_gemm_mma<<<gemm_blocks, 256, SMEM_GEMM>>>(1, bias2, out, 0);
}